// round 2
// baseline (speedup 1.0000x reference)
#include <cuda_runtime.h>
#include <cstdint>
#include <math.h>

// Problem constants (fixed shapes from reference)
#define B_    16
#define CIN   256
#define COUT  256
#define KW    3
#define L_    4096
#define NR    5
#define CK    (CIN * KW)        // 768
#define MROWS (NR * COUT)       // 1280
#define BL    (B_ * L_)         // 65536

// Scratch (device globals — allocation-free per harness rules)
__device__ float g_fr[NR * BL];                          // fr[n][b*L + l]
__device__ float g_Y[(size_t)B_ * MROWS * (size_t)L_];   // Y[b][m][l], m = n*COUT + o

// ---------------------------------------------------------------------------
// packed f32x2 helpers (sm_103a FFMA2 path)
// ---------------------------------------------------------------------------
__device__ __forceinline__ unsigned long long fma2(unsigned long long a,
                                                   unsigned long long b,
                                                   unsigned long long c) {
    unsigned long long d;
    asm("fma.rn.f32x2 %0, %1, %2, %3;" : "=l"(d) : "l"(a), "l"(b), "l"(c));
    return d;
}
__device__ __forceinline__ unsigned long long dup2(float v) {
    unsigned long long d;
    asm("mov.b64 %0, {%1, %1};" : "=l"(d) : "f"(v), "f"(v));
    return d;
}

// ---------------------------------------------------------------------------
// Kernel 1: controller -> softmax firing strengths
// grid (L/256, B), block 256. One thread per (b, l).
// ---------------------------------------------------------------------------
__global__ void __launch_bounds__(256) ctrl_kernel(
    const float* __restrict__ x,       // (B, CIN, L)
    const float* __restrict__ cw,      // (CK, NR)
    const float* __restrict__ cb)      // (NR,)
{
    __shared__ float sw[CK * NR];      // 3840 floats = 15 KB
    const int tid = threadIdx.x;
    for (int i = tid; i < CK * NR; i += 256) sw[i] = cw[i];
    __syncthreads();

    const int b = blockIdx.y;
    const int l = blockIdx.x * 256 + tid;
    const float* xb = x + (size_t)b * CIN * L_;

    float acc[NR];
#pragma unroll
    for (int n = 0; n < NR; n++) acc[n] = cb[n];

    for (int c = 0; c < CIN; c++) {
        const float* xc = xb + (size_t)c * L_;
        const float x0 = (l >= 2) ? xc[l - 2] : 0.0f;
        const float x1 = (l >= 1) ? xc[l - 1] : 0.0f;
        const float x2 = xc[l];
        const float* w0 = &sw[(c * 3 + 0) * NR];
        const float* w1 = &sw[(c * 3 + 1) * NR];
        const float* w2 = &sw[(c * 3 + 2) * NR];
#pragma unroll
        for (int n = 0; n < NR; n++)
            acc[n] += x0 * w0[n] + x1 * w1[n] + x2 * w2[n];
    }

    // softmax over NR
    float mx = acc[0];
#pragma unroll
    for (int n = 1; n < NR; n++) mx = fmaxf(mx, acc[n]);
    float e[NR], s = 0.0f;
#pragma unroll
    for (int n = 0; n < NR; n++) { e[n] = expf(acc[n] - mx); s += e[n]; }
    const float inv = 1.0f / s;
    const size_t bl = (size_t)b * L_ + l;
#pragma unroll
    for (int n = 0; n < NR; n++) g_fr[(size_t)n * BL + bl] = e[n] * inv;
}

// ---------------------------------------------------------------------------
// Kernel 2: main GEMM  Y[b] = W(1280x768) @ Patches[b](768x4096)
// Patch element (ck, l) = x[b, ck/3, l + ck%3 - 2]  (causal zero pad)
// 128x128x16 tile, 256 threads, 8x8 per thread, FFMA2 inner loop.
// ---------------------------------------------------------------------------
#define BM 128
#define BN 128
#define BK 16
#define TM 8
#define TN 8

__global__ void __launch_bounds__(256, 2) gemm_kernel(
    const float* __restrict__ A,   // base_kernels flattened (MROWS, CK)
    const float* __restrict__ x)   // (B, CIN, L)
{
    __shared__ unsigned long long As2[BK][BM + 2];  // A value duplicated {a,a}
    __shared__ float Bs[BK][BN + 4];

    const int tid = threadIdx.x;
    const int b  = blockIdx.z;
    const int m0 = blockIdx.y * BM;
    const int l0 = blockIdx.x * BN;
    const float* xb = x + (size_t)b * CIN * L_;

    // compute-phase coords
    const int tm0 = (tid / 16) * TM;
    const int tn0 = (tid % 16) * TN;

    // A load mapping: 2048 elems / 256 thr = 8 each (two float4)
    const int aRow = tid >> 1;             // 0..127
    const int aCol = (tid & 1) * 8;        // 0 or 8
    // B load mapping: 8 passes of 2 rows x 128 cols
    const int bCol    = tid & 127;
    const int bRowOff = tid >> 7;          // 0 or 1

    unsigned long long acc[TM][TN / 2];
#pragma unroll
    for (int i = 0; i < TM; i++)
#pragma unroll
        for (int j = 0; j < TN / 2; j++) acc[i][j] = 0ull;

    for (int kt = 0; kt < CK; kt += BK) {
        // --- load A tile (duplicated into f32x2) ---
        const float* Ap = A + (size_t)(m0 + aRow) * CK + kt + aCol;
        const float4 av0 = *reinterpret_cast<const float4*>(Ap);
        const float4 av1 = *reinterpret_cast<const float4*>(Ap + 4);
        As2[aCol + 0][aRow] = dup2(av0.x);
        As2[aCol + 1][aRow] = dup2(av0.y);
        As2[aCol + 2][aRow] = dup2(av0.z);
        As2[aCol + 3][aRow] = dup2(av0.w);
        As2[aCol + 4][aRow] = dup2(av1.x);
        As2[aCol + 5][aRow] = dup2(av1.y);
        As2[aCol + 6][aRow] = dup2(av1.z);
        As2[aCol + 7][aRow] = dup2(av1.w);

        // --- load B tile (patch generation on the fly) ---
#pragma unroll
        for (int p = 0; p < 8; p++) {
            const int r  = p * 2 + bRowOff;
            const int ck = kt + r;
            const int c  = ck / 3;
            const int k  = ck - c * 3;
            const int gl = l0 + bCol + k - 2;   // gl < L always; gl >= 0 only edge
            float v = 0.0f;
            if (gl >= 0) v = xb[(size_t)c * L_ + gl];
            Bs[r][bCol] = v;
        }
        __syncthreads();

        // --- compute ---
#pragma unroll
        for (int kk = 0; kk < BK; kk++) {
            unsigned long long a[TM];
            const unsigned long long* ar = &As2[kk][tm0];
#pragma unroll
            for (int i = 0; i < TM; i++) a[i] = ar[i];
            unsigned long long bf[TN / 2];
            const unsigned long long* br =
                reinterpret_cast<const unsigned long long*>(&Bs[kk][tn0]);
#pragma unroll
            for (int j = 0; j < TN / 2; j++) bf[j] = br[j];
#pragma unroll
            for (int i = 0; i < TM; i++)
#pragma unroll
                for (int j = 0; j < TN / 2; j++)
                    acc[i][j] = fma2(a[i], bf[j], acc[i][j]);
        }
        __syncthreads();
    }

    // --- epilogue: store Y tile ---
    float* Yb = g_Y + ((size_t)b * MROWS + m0) * L_ + l0;
#pragma unroll
    for (int i = 0; i < TM; i++) {
        unsigned long long* dst =
            reinterpret_cast<unsigned long long*>(Yb + (size_t)(tm0 + i) * L_ + tn0);
#pragma unroll
        for (int j = 0; j < TN / 2; j++) dst[j] = acc[i][j];
    }
}

// ---------------------------------------------------------------------------
// Kernel 3: mix  out[b,o,l] = sum_n fr[b,l,n] * (Y[b,n,o,l] + bias[n,o])
// grid (L/256, COUT, B), block 256.
// ---------------------------------------------------------------------------
__global__ void __launch_bounds__(256) mix_kernel(
    const float* __restrict__ bias,   // (NR, COUT)
    float* __restrict__ out)          // (B, COUT, L)
{
    const int l = blockIdx.x * 256 + threadIdx.x;
    const int o = blockIdx.y;
    const int b = blockIdx.z;
    const size_t bl = (size_t)b * L_ + l;

    float r = 0.0f;
#pragma unroll
    for (int n = 0; n < NR; n++) {
        const float f = g_fr[(size_t)n * BL + bl];
        const float y = g_Y[(((size_t)b * NR + n) * COUT + o) * L_ + l];
        r += f * (y + __ldg(&bias[n * COUT + o]));
    }
    out[((size_t)b * COUT + o) * L_ + l] = r;
}

// ---------------------------------------------------------------------------
// launch
// ---------------------------------------------------------------------------
extern "C" void kernel_launch(void* const* d_in, const int* in_sizes, int n_in,
                              void* d_out, int out_size) {
    const float* x  = (const float*)d_in[0];  // (16, 256, 4096)
    const float* bk = (const float*)d_in[1];  // (5, 256, 256, 3)
    const float* bb = (const float*)d_in[2];  // (5, 256)
    const float* cw = (const float*)d_in[3];  // (768, 5)
    const float* cb = (const float*)d_in[4];  // (5,)
    float* out = (float*)d_out;               // (16, 256, 4096)

    // K1: controller softmax
    {
        dim3 grid(L_ / 256, B_);
        ctrl_kernel<<<grid, 256>>>(x, cw, cb);
    }
    // K2: main GEMM into g_Y
    {
        dim3 grid(L_ / BN, MROWS / BM, B_);   // (32, 10, 16)
        gemm_kernel<<<grid, 256>>>(bk, x);
    }
    // K3: mix
    {
        dim3 grid(L_ / 256, COUT, B_);
        mix_kernel<<<grid, 256>>>(bb, out);
    }
}

// round 3
// speedup vs baseline: 3.0957x; 3.0957x over previous
#include <cuda_runtime.h>
#include <cstdint>
#include <math.h>

#define B_    16
#define CIN   256
#define COUT  256
#define KW    3
#define L_    4096
#define NR    5
#define CK    768            // CIN*KW
#define MROWS 1280           // NR*COUT
#define BL    (B_ * L_)

// ---------------- scratch (device globals; allocation-free) ----------------
__device__ float g_fr[NR * BL];                             // fr[n][b*L+l]
__device__ float g_A[MROWS * CK];                           // tf32 weights [m][ck]
__device__ float g_P[(size_t)B_ * L_ * CK];                 // tf32 patches [b][l][ck]
__device__ float g_Y[(size_t)B_ * MROWS * (size_t)L_];      // conv out [b][m][l]

// ---------------- helpers ----------------
__device__ __forceinline__ float to_tf32(float v) {
    uint32_t b;
    asm("cvt.rna.tf32.f32 %0, %1;" : "=r"(b) : "f"(v));
    return __uint_as_float(b);
}
__device__ __forceinline__ void cp16(uint32_t dst, const void* src) {
    asm volatile("cp.async.cg.shared.global [%0], [%1], 16;" :: "r"(dst), "l"(src));
}
__device__ __forceinline__ void cp_commit() {
    asm volatile("cp.async.commit_group;");
}
__device__ __forceinline__ void cp_wait1() {
    asm volatile("cp.async.wait_group 1;");
}
__device__ __forceinline__ void ldsm4(uint32_t* r, uint32_t addr) {
    asm volatile("ldmatrix.sync.aligned.m8n8.x4.shared.b16 {%0,%1,%2,%3}, [%4];"
                 : "=r"(r[0]), "=r"(r[1]), "=r"(r[2]), "=r"(r[3]) : "r"(addr));
}
__device__ __forceinline__ void mma_tf32(float* d, const uint32_t* a, uint32_t b0, uint32_t b1) {
    asm volatile("mma.sync.aligned.m16n8k8.row.col.f32.tf32.tf32.f32 "
                 "{%0,%1,%2,%3}, {%4,%5,%6,%7}, {%8,%9}, {%0,%1,%2,%3};"
                 : "+f"(d[0]), "+f"(d[1]), "+f"(d[2]), "+f"(d[3])
                 : "r"(a[0]), "r"(a[1]), "r"(a[2]), "r"(a[3]), "r"(b0), "r"(b1));
}

// ---------------------------------------------------------------------------
// prep A: tf32-round weights (already [m][ck] contiguous)
// ---------------------------------------------------------------------------
__global__ void __launch_bounds__(256) prepA_kernel(const float* __restrict__ w) {
    int i = blockIdx.x * 256 + threadIdx.x;
    if (i < MROWS * CK) g_A[i] = to_tf32(w[i]);
}

// ---------------------------------------------------------------------------
// prep P: g_P[b][l][ck] = tf32(x[b][ck/3][l + ck%3 - 2]), causal zero-pad
// block: 256 thr; tile = 64 channels x 32 l
// ---------------------------------------------------------------------------
__global__ void __launch_bounds__(256) prepP_kernel(const float* __restrict__ x) {
    __shared__ float xs[64][34];
    const int tid = threadIdx.x;
    const int l0 = blockIdx.x * 32;
    const int c0 = blockIdx.y * 64;
    const int b  = blockIdx.z;

    for (int idx = tid; idx < 64 * 34; idx += 256) {
        const int c = idx / 34, j = idx % 34;
        const int gl = l0 - 2 + j;
        xs[c][j] = (gl >= 0) ? x[((size_t)(b * CIN + c0 + c)) * L_ + gl] : 0.0f;
    }
    __syncthreads();

    float* Pb = g_P + ((size_t)b * L_ + l0) * CK + c0 * 3;
    for (int idx = tid; idx < 32 * 192; idx += 256) {
        const int li = idx / 192, q = idx % 192;
        const int c = q / 3, k = q - 3 * c;
        Pb[(size_t)li * CK + q] = to_tf32(xs[c][li + k]);
    }
}

// ---------------------------------------------------------------------------
// controller: 4 l per thread, vector loads, full fp32
// ---------------------------------------------------------------------------
__global__ void __launch_bounds__(128) ctrl_kernel(
    const float* __restrict__ x, const float* __restrict__ cw,
    const float* __restrict__ cb)
{
    __shared__ float sw[CK * NR];
    const int tid = threadIdx.x;
    for (int i = tid; i < CK * NR; i += 128) sw[i] = cw[i];
    __syncthreads();

    const int b  = blockIdx.y;
    const int l4 = (blockIdx.x * 128 + tid) * 4;
    const float* xb = x + (size_t)b * CIN * L_;

    float acc[4][NR];
#pragma unroll
    for (int li = 0; li < 4; li++)
#pragma unroll
        for (int n = 0; n < NR; n++) acc[li][n] = cb[n];

    for (int c = 0; c < CIN; c++) {
        const float* xc = xb + (size_t)c * L_ + l4;
        float v[6];
        if (l4 >= 2) {
            const float2 u = *reinterpret_cast<const float2*>(xc - 2);
            v[0] = u.x; v[1] = u.y;
        } else { v[0] = 0.0f; v[1] = 0.0f; }
        const float4 w4 = *reinterpret_cast<const float4*>(xc);
        v[2] = w4.x; v[3] = w4.y; v[4] = w4.z; v[5] = w4.w;

        const float* wr = &sw[c * 3 * NR];
#pragma unroll
        for (int li = 0; li < 4; li++)
#pragma unroll
            for (int n = 0; n < NR; n++)
                acc[li][n] += v[li] * wr[n] + v[li + 1] * wr[NR + n] + v[li + 2] * wr[2 * NR + n];
    }

#pragma unroll
    for (int li = 0; li < 4; li++) {
        float mx = acc[li][0];
#pragma unroll
        for (int n = 1; n < NR; n++) mx = fmaxf(mx, acc[li][n]);
        float e[NR], s = 0.0f;
#pragma unroll
        for (int n = 0; n < NR; n++) { e[n] = __expf(acc[li][n] - mx); s += e[n]; }
        const float inv = 1.0f / s;
        const size_t bl = (size_t)b * L_ + l4 + li;
#pragma unroll
        for (int n = 0; n < NR; n++) g_fr[(size_t)n * BL + bl] = e[n] * inv;
    }
}

// ---------------------------------------------------------------------------
// GEMM: Y[b](1280x4096) = A(1280x768) @ P[b]^T ; tf32 mma.sync
// block 128x128x32, 4 warps (2x2), warp tile 64x64, double-buffered cp.async
// ---------------------------------------------------------------------------
#define GBM 128
#define GBN 128
#define GBK 32
#define KROW 36                  // padded row stride (floats): 144B = 9 x 16B
#define TILEF (128 * KROW)       // floats per buffer

__global__ void __launch_bounds__(128) gemm_kernel(int dummy) {
    extern __shared__ float smem[];
    float* As = smem;                 // [2][128][36]
    float* Bs = smem + 2 * TILEF;     // [2][128][36]
    const uint32_t sbase = (uint32_t)__cvta_generic_to_shared(smem);
    const uint32_t aBase = sbase;
    const uint32_t bBase = sbase + 2 * TILEF * 4;

    const int tid  = threadIdx.x;
    const int lane = tid & 31;
    const int wid  = tid >> 5;
    const int warp_m = wid >> 1;      // 0..1
    const int warp_n = wid & 1;       // 0..1

    const int b  = blockIdx.z;
    const int m0 = blockIdx.y * GBM;
    const int l0 = blockIdx.x * GBN;

    const float* Ag = g_A + (size_t)m0 * CK;
    const float* Pg = g_P + ((size_t)b * L_ + l0) * CK;

    // tile loader: 1024 16B-chunks per operand, 8 per thread
    auto load_tile = [&](int buf, int kt) {
#pragma unroll
        for (int i = 0; i < 8; i++) {
            const int idx = tid + i * 128;
            const int row = idx >> 3;
            const int kc  = (idx & 7) * 4;
            cp16(aBase + (uint32_t)(buf * TILEF + row * KROW + kc) * 4,
                 Ag + (size_t)row * CK + kt + kc);
            cp16(bBase + (uint32_t)(buf * TILEF + row * KROW + kc) * 4,
                 Pg + (size_t)row * CK + kt + kc);
        }
        cp_commit();
    };

    float acc[4][8][4];
#pragma unroll
    for (int mt = 0; mt < 4; mt++)
#pragma unroll
        for (int nt = 0; nt < 8; nt++)
#pragma unroll
            for (int r = 0; r < 4; r++) acc[mt][nt][r] = 0.0f;

    load_tile(0, 0);

    int buf = 0;
    const int arow = warp_m * 64 + (lane & 15);
    const int brow = warp_n * 64 + (lane & 15);
    const int koff = (lane >> 4) * 4;

    for (int kt = 0; kt < CK; kt += GBK) {
        if (kt + GBK < CK) load_tile(buf ^ 1, kt + GBK);
        cp_wait1();
        __syncthreads();

#pragma unroll
        for (int ks = 0; ks < 4; ks++) {
            const int k0 = ks * 8 + koff;
            uint32_t a[4][4];
#pragma unroll
            for (int mt = 0; mt < 4; mt++)
                ldsm4(a[mt], aBase + (uint32_t)(buf * TILEF + (arow + mt * 16) * KROW + k0) * 4);
            uint32_t bb[4][4];
#pragma unroll
            for (int np = 0; np < 4; np++)
                ldsm4(bb[np], bBase + (uint32_t)(buf * TILEF + (brow + np * 16) * KROW + k0) * 4);
#pragma unroll
            for (int mt = 0; mt < 4; mt++)
#pragma unroll
                for (int np = 0; np < 4; np++) {
                    mma_tf32(acc[mt][2 * np],     a[mt], bb[np][0], bb[np][2]);
                    mma_tf32(acc[mt][2 * np + 1], a[mt], bb[np][1], bb[np][3]);
                }
        }
        __syncthreads();
        buf ^= 1;
    }

    // epilogue
    float* Yb = g_Y + ((size_t)b * MROWS) * L_;
    const int mrow = m0 + warp_m * 64 + (lane >> 2);
    const int lcol = l0 + warp_n * 64 + (lane & 3) * 2;
#pragma unroll
    for (int mt = 0; mt < 4; mt++) {
#pragma unroll
        for (int nt = 0; nt < 8; nt++) {
            const int m = mrow + mt * 16;
            const int l = lcol + nt * 8;
            float2* p0 = reinterpret_cast<float2*>(Yb + (size_t)m * L_ + l);
            float2* p1 = reinterpret_cast<float2*>(Yb + (size_t)(m + 8) * L_ + l);
            *p0 = make_float2(acc[mt][nt][0], acc[mt][nt][1]);
            *p1 = make_float2(acc[mt][nt][2], acc[mt][nt][3]);
        }
    }
}

// ---------------------------------------------------------------------------
// mix: out[b,o,l] = sum_n fr[b,l,n] * (Y[b,n,o,l] + bias[n,o])
// block = 128 l positions; fr cached in regs; sweep o
// ---------------------------------------------------------------------------
__global__ void __launch_bounds__(128) mix_kernel(
    const float* __restrict__ bias, float* __restrict__ out)
{
    __shared__ float sb[NR * COUT];
    const int tid = threadIdx.x;
    for (int i = tid; i < NR * COUT; i += 128) sb[i] = bias[i];

    const int b = blockIdx.y;
    const int l = blockIdx.x * 128 + tid;
    const size_t bl = (size_t)b * L_ + l;

    float f[NR];
#pragma unroll
    for (int n = 0; n < NR; n++) f[n] = g_fr[(size_t)n * BL + bl];
    __syncthreads();

    const float* Yb = g_Y + (size_t)b * MROWS * L_ + l;
    float* ob = out + (size_t)b * COUT * L_ + l;

#pragma unroll 4
    for (int o = 0; o < COUT; o++) {
        float r = 0.0f;
#pragma unroll
        for (int n = 0; n < NR; n++)
            r += f[n] * (Yb[(size_t)(n * COUT + o) * L_] + sb[n * COUT + o]);
        ob[(size_t)o * L_] = r;
    }
}

// ---------------------------------------------------------------------------
// launch
// ---------------------------------------------------------------------------
extern "C" void kernel_launch(void* const* d_in, const int* in_sizes, int n_in,
                              void* d_out, int out_size) {
    const float* x  = (const float*)d_in[0];
    const float* bk = (const float*)d_in[1];
    const float* bb = (const float*)d_in[2];
    const float* cw = (const float*)d_in[3];
    const float* cb = (const float*)d_in[4];
    float* out = (float*)d_out;

    static int smem_set = 0;
    if (!smem_set) {
        cudaFuncSetAttribute(gemm_kernel, cudaFuncAttributeMaxDynamicSharedMemorySize,
                             4 * TILEF * 4);
        smem_set = 1;
    }

    prepA_kernel<<<(MROWS * CK + 255) / 256, 256>>>(bk);
    prepP_kernel<<<dim3(L_ / 32, CIN / 64, B_), 256>>>(x);
    ctrl_kernel<<<dim3(L_ / 512, B_), 128>>>(x, cw, cb);
    gemm_kernel<<<dim3(L_ / GBN, MROWS / GBM, B_), 128, 4 * TILEF * 4>>>(0);
    mix_kernel<<<dim3(L_ / 128, B_), 128>>>(bb, out);
}